// round 10
// baseline (speedup 1.0000x reference)
#include <cuda_runtime.h>

// out[bh][q*96+v] = K[bh,3,q] * u[v];  u = scale * (q3 @ V) @ W3
// 96 blocks x 576 threads; each block computes TWO bh pairs and loads the
// shared W3 slice ONCE per thread (halves chip-wide W traffic).

#define SD    96
#define C4    24      // float4 columns per row
#define KG    24      // k groups
#define KSPAN 4       // 96 / KG
#define NT    (C4 * KG)   // 576

__global__ __launch_bounds__(NT, 1) void mma73_kernel(
    const float* __restrict__ Q,
    const float* __restrict__ K,
    const float* __restrict__ V,
    const float* __restrict__ DW,
    const int*   __restrict__ uidx_p,
    float* __restrict__ out)
{
    const int tid = threadIdx.x;
    const int c4  = tid % C4;     // 0..23
    const int grp = tid / C4;     // 0..23
    const int bh0 = blockIdx.x * 2;       // even bh
    const int bh1 = bh0 + 1;

    __shared__ float t_s[2][SD];
    __shared__ __align__(16) float u_s[2][SD];
    __shared__ __align__(16) float4 part4[2][KG][C4];

    const int uidx = __ldg(uidx_p);

    const float4* __restrict__ V0 = (const float4*)(V + (size_t)bh0 * SD * SD);
    const float4* __restrict__ V1 = (const float4*)(V + (size_t)bh1 * SD * SD);
    const float4* __restrict__ W4 = (const float4*)(DW + (size_t)uidx * SD * SD);
    const size_t qb0 = ((size_t)bh0 * SD + 3) * SD;
    const size_t qb1 = ((size_t)bh1 * SD + 3) * SD;

    // ---- front-batched independent loads: 12 LDG.128 + 16 broadcast LDG ----
    float4 w_r[KSPAN], v0_r[KSPAN], v1_r[KSPAN];
    float  q0_r[KSPAN], q1_r[KSPAN], k0_r[KSPAN], k1_r[KSPAN];
    #pragma unroll
    for (int j = 0; j < KSPAN; ++j) {
        const int row = (grp * KSPAN + j) * C4 + c4;
        v0_r[j] = V0[row];
        v1_r[j] = V1[row];
        w_r[j]  = W4[row];
    }
    #pragma unroll
    for (int j = 0; j < KSPAN; ++j) {
        q0_r[j] = __ldg(Q + qb0 + grp * KSPAN + j);
        q1_r[j] = __ldg(Q + qb1 + grp * KSPAN + j);
        k0_r[j] = __ldg(K + qb0 + j * KG + grp);
        k1_r[j] = __ldg(K + qb1 + j * KG + grp);
    }

    // ---- phase 1 partials for both halves (sync-free start) ----
    {
        float4 a = make_float4(0.f, 0.f, 0.f, 0.f);
        float4 b = make_float4(0.f, 0.f, 0.f, 0.f);
        #pragma unroll
        for (int j = 0; j < KSPAN; ++j) {
            a.x += q0_r[j] * v0_r[j].x;  a.y += q0_r[j] * v0_r[j].y;
            a.z += q0_r[j] * v0_r[j].z;  a.w += q0_r[j] * v0_r[j].w;
            b.x += q1_r[j] * v1_r[j].x;  b.y += q1_r[j] * v1_r[j].y;
            b.z += q1_r[j] * v1_r[j].z;  b.w += q1_r[j] * v1_r[j].w;
        }
        part4[0][grp][c4] = a;
        part4[1][grp][c4] = b;
    }
    __syncthreads();

    // ---- t reduce: 192 threads (96 per half) ----
    if (tid < 2 * SD) {
        const int h = tid / SD, i = tid % SD;
        const float* p = (const float*)part4[h];   // [KG][SD]
        float s = p[i];
        #pragma unroll
        for (int g = 1; g < KG; ++g) s += p[g * SD + i];
        t_s[h][i] = s;
    }
    __syncthreads();

    // ---- phase 2 partials for both halves (shared w_r) ----
    {
        float4 a = make_float4(0.f, 0.f, 0.f, 0.f);
        float4 b = make_float4(0.f, 0.f, 0.f, 0.f);
        #pragma unroll
        for (int j = 0; j < KSPAN; ++j) {
            const float t0 = t_s[0][grp * KSPAN + j];
            const float t1 = t_s[1][grp * KSPAN + j];
            a.x += t0 * w_r[j].x;  a.y += t0 * w_r[j].y;
            a.z += t0 * w_r[j].z;  a.w += t0 * w_r[j].w;
            b.x += t1 * w_r[j].x;  b.y += t1 * w_r[j].y;
            b.z += t1 * w_r[j].z;  b.w += t1 * w_r[j].w;
        }
        part4[0][grp][c4] = a;
        part4[1][grp][c4] = b;
    }
    __syncthreads();

    // ---- u reduce: 192 threads ----
    if (tid < 2 * SD) {
        const int h = tid / SD, i = tid % SD;
        const float* p = (const float*)part4[h];
        float s = p[i];
        #pragma unroll
        for (int g = 1; g < KG; ++g) s += p[g * SD + i];
        u_s[h][i] = s * 0.10206207261596575f;   // 1/sqrt(96)
    }
    __syncthreads();

    // ---- phase 3: outer products, 8 STG.128 per thread ----
    float4* __restrict__ O0 = (float4*)(out + (size_t)bh0 * SD * SD);
    float4* __restrict__ O1 = (float4*)(out + (size_t)bh1 * SD * SD);
    const float4 ua = ((const float4*)u_s[0])[c4];
    const float4 ub = ((const float4*)u_s[1])[c4];
    #pragma unroll
    for (int r = 0; r < KSPAN; ++r) {
        const int idx = (r * KG + grp) * C4 + c4;
        const float ka = k0_r[r], kb = k1_r[r];
        float4 oa, ob;
        oa.x = ka * ua.x;  oa.y = ka * ua.y;  oa.z = ka * ua.z;  oa.w = ka * ua.w;
        ob.x = kb * ub.x;  ob.y = kb * ub.y;  ob.z = kb * ub.z;  ob.w = kb * ub.w;
        O0[idx] = oa;
        O1[idx] = ob;
    }
}

extern "C" void kernel_launch(void* const* d_in, const int* in_sizes, int n_in,
                              void* d_out, int out_size)
{
    const float* Q  = (const float*)d_in[0];
    const float* K  = (const float*)d_in[1];
    const float* V  = (const float*)d_in[2];
    const float* DW = (const float*)d_in[3];
    const int* uidx = (const int*)d_in[4];
    float* out      = (float*)d_out;

    mma73_kernel<<<96, NT>>>(Q, K, V, DW, uidx, out);
}